// round 2
// baseline (speedup 1.0000x reference)
#include <cuda_runtime.h>

// Problem constants
#define NB      131072      // batch rows
#define D       256         // feature dim
#define LEAVES  4
#define MID     2

constexpr int TILE_M   = 64;          // rows per block
constexpr int KC       = 16;          // K-chunk streamed through smem
constexpr int THREADS  = 256;
constexpr int SX_STRIDE = D + 8;      // 264: 16B-aligned rows, banks shift 8/row

// dynamic smem layout (floats)
constexpr int OFF_SX    = 0;
constexpr int OFF_SW    = OFF_SX + TILE_M * SX_STRIDE;        // 16896
constexpr int OFF_SWG   = OFF_SW + KC * D;                    // +4096
constexpr int OFF_BLEAF = OFF_SWG + D * LEAVES;               // +1024
constexpr int OFF_BMID  = OFF_BLEAF + LEAVES * D;             // +1024
constexpr int OFF_BROOT = OFF_BMID + MID * D;                 // +512
constexpr int OFF_LOG   = OFF_BROOT + D;                      // +256
constexpr int OFF_IDX   = OFF_LOG + TILE_M * LEAVES;          // +256
constexpr int SMEM_FLOATS = OFF_IDX + TILE_M;                 // + 64 (as ints)
constexpr int SMEM_BYTES  = SMEM_FLOATS * (int)sizeof(float); // 96512

// One GEMM pass: acc[8][8] += (masked A-tile in sX) @ (W chunk streamed via sW).
// A rows not belonging to the current expert are zeroed via m[], so accumulating
// across expert passes yields exactly the per-row-selected expert's output.
template <bool MASKED>
__device__ __forceinline__
void gemm_pass(const float* __restrict__ Wglob, float* sW, const float* sX,
               const float m[8], float (&acc)[8][8], int tid, int r0, int c0)
{
#pragma unroll 1
    for (int kc = 0; kc < D; kc += KC) {
        __syncthreads();   // previous chunk's consumers done before overwrite
        const float4* wg4 = reinterpret_cast<const float4*>(Wglob + (size_t)kc * D);
        float4* sW4 = reinterpret_cast<float4*>(sW);
#pragma unroll
        for (int i = 0; i < (KC * D / 4) / THREADS; i++)   // 4 x float4 per thread
            sW4[tid + i * THREADS] = wg4[tid + i * THREADS];
        __syncthreads();
#pragma unroll
        for (int k = 0; k < KC; k++) {
            float a[8];
#pragma unroll
            for (int i = 0; i < 8; i++) {
                float v = sX[(r0 + i) * SX_STRIDE + kc + k];   // warp-broadcast
                a[i] = MASKED ? v * m[i] : v;
            }
            float4 b0 = *reinterpret_cast<const float4*>(&sW[k * D + c0]);
            float4 b1 = *reinterpret_cast<const float4*>(&sW[k * D + c0 + 4]);
            float bb[8] = {b0.x, b0.y, b0.z, b0.w, b1.x, b1.y, b1.z, b1.w};
#pragma unroll
            for (int i = 0; i < 8; i++)
#pragma unroll
                for (int j = 0; j < 8; j++)
                    acc[i][j] = fmaf(a[i], bb[j], acc[i][j]);
        }
    }
}

__global__ void __launch_bounds__(THREADS, 2)
tree_fused_kernel(const float* __restrict__ x,
                  const float* __restrict__ Wg,
                  const float* __restrict__ bg,
                  const float* __restrict__ W_leaf,
                  const float* __restrict__ b_leaf,
                  const float* __restrict__ W_mid,
                  const float* __restrict__ b_mid,
                  const float* __restrict__ W_root,
                  const float* __restrict__ b_root,
                  float* __restrict__ out)
{
    extern __shared__ float sm[];
    float* sX    = sm + OFF_SX;     // x tile, later reused for h1 / h2
    float* sW    = sm + OFF_SW;     // streamed weight chunk
    float* sWg   = sm + OFF_SWG;
    float* sBlf  = sm + OFF_BLEAF;
    float* sBmd  = sm + OFF_BMID;
    float* sBrt  = sm + OFF_BROOT;
    float* sLog  = sm + OFF_LOG;
    int*   sIdx  = reinterpret_cast<int*>(sm + OFF_IDX);

    const int tid = threadIdx.x;
    const size_t row0 = (size_t)blockIdx.x * TILE_M;
    const int tx = tid & 31, ty = tid >> 5;
    const int r0 = ty * 8, c0 = tx * 8;

    // ---- load x tile (64x256) + small params into smem ----
    {
        const float4* xg = reinterpret_cast<const float4*>(x + row0 * D);
#pragma unroll
        for (int i = 0; i < (TILE_M * D / 4) / THREADS; i++) {   // 16 per thread
            int li = tid + i * THREADS;
            int r = li / (D / 4), c4 = li % (D / 4);
            float4 v = xg[r * (D / 4) + c4];
            float* dst = &sX[r * SX_STRIDE + c4 * 4];
            dst[0] = v.x; dst[1] = v.y; dst[2] = v.z; dst[3] = v.w;
        }
    }
    for (int i = tid; i < D * LEAVES; i += THREADS) sWg[i]  = Wg[i];
    for (int i = tid; i < LEAVES * D; i += THREADS) sBlf[i] = b_leaf[i];
    for (int i = tid; i < MID * D;    i += THREADS) sBmd[i] = b_mid[i];
    for (int i = tid; i < D;          i += THREADS) sBrt[i] = b_root[i];
    __syncthreads();

    // ---- gate: logits + argmax (first-max wins, matching jnp.argmax) ----
    {
        int r = tid & (TILE_M - 1);
        int e = tid >> 6;                       // 0..3
        float acc = bg[e];
        const float* xr = &sX[r * SX_STRIDE];
        for (int d = 0; d < D; d++) acc = fmaf(xr[d], sWg[d * LEAVES + e], acc);
        sLog[r * LEAVES + e] = acc;
    }
    __syncthreads();
    if (tid < TILE_M) {
        float best = sLog[tid * LEAVES];
        int bi = 0;
#pragma unroll
        for (int e = 1; e < LEAVES; e++) {
            float v = sLog[tid * LEAVES + e];
            if (v > best) { best = v; bi = e; }
        }
        sIdx[tid] = bi;
    }
    __syncthreads();

    float acc[8][8];
#pragma unroll
    for (int i = 0; i < 8; i++)
#pragma unroll
        for (int j = 0; j < 8; j++) acc[i][j] = 0.f;
    float m[8];

    // ---- leaf layer: 4 masked passes into one accumulator ----
    for (int e = 0; e < LEAVES; e++) {
#pragma unroll
        for (int i = 0; i < 8; i++) m[i] = (sIdx[r0 + i] == e) ? 1.f : 0.f;
        gemm_pass<true>(W_leaf + (size_t)e * D * D, sW, sX, m, acc, tid, r0, c0);
    }
    __syncthreads();   // everyone done reading x before h1 overwrites sX
#pragma unroll
    for (int i = 0; i < 8; i++) {
        int e = sIdx[r0 + i];
#pragma unroll
        for (int j = 0; j < 8; j++) {
            float v = fmaxf(acc[i][j] + sBlf[e * D + c0 + j], 0.f);
            sX[(r0 + i) * SX_STRIDE + c0 + j] = v;
            acc[i][j] = 0.f;
        }
    }
    __syncthreads();

    // ---- mid layer: 2 masked passes (parent = idx >> 1) ----
    for (int p = 0; p < MID; p++) {
#pragma unroll
        for (int i = 0; i < 8; i++) m[i] = ((sIdx[r0 + i] >> 1) == p) ? 1.f : 0.f;
        gemm_pass<true>(W_mid + (size_t)p * D * D, sW, sX, m, acc, tid, r0, c0);
    }
    __syncthreads();
#pragma unroll
    for (int i = 0; i < 8; i++) {
        int p = sIdx[r0 + i] >> 1;
#pragma unroll
        for (int j = 0; j < 8; j++) {
            float v = fmaxf(acc[i][j] + sBmd[p * D + c0 + j], 0.f);
            sX[(r0 + i) * SX_STRIDE + c0 + j] = v;
            acc[i][j] = 0.f;
        }
    }
    __syncthreads();

    // ---- root layer (shared) + write out ----
    gemm_pass<false>(W_root, sW, sX, m, acc, tid, r0, c0);
#pragma unroll
    for (int i = 0; i < 8; i++) {
        float v[8];
#pragma unroll
        for (int j = 0; j < 8; j++)
            v[j] = fmaxf(acc[i][j] + sBrt[c0 + j], 0.f);
        float4* o = reinterpret_cast<float4*>(out + (row0 + r0 + i) * D + c0);
        o[0] = make_float4(v[0], v[1], v[2], v[3]);
        o[1] = make_float4(v[4], v[5], v[6], v[7]);
    }
}

extern "C" void kernel_launch(void* const* d_in, const int* in_sizes, int n_in,
                              void* d_out, int out_size)
{
    const float* x      = (const float*)d_in[0];
    const float* Wg     = (const float*)d_in[1];
    const float* bg     = (const float*)d_in[2];
    const float* W_leaf = (const float*)d_in[3];
    const float* b_leaf = (const float*)d_in[4];
    const float* W_mid  = (const float*)d_in[5];
    const float* b_mid  = (const float*)d_in[6];
    const float* W_root = (const float*)d_in[7];
    const float* b_root = (const float*)d_in[8];
    float* out = (float*)d_out;

    // idempotent, non-stream API: safe during graph capture
    cudaFuncSetAttribute(tree_fused_kernel,
                         cudaFuncAttributeMaxDynamicSharedMemorySize, SMEM_BYTES);

    tree_fused_kernel<<<NB / TILE_M, THREADS, SMEM_BYTES>>>(
        x, Wg, bg, W_leaf, b_leaf, W_mid, b_mid, W_root, b_root, out);
}

// round 3
// speedup vs baseline: 2.1563x; 2.1563x over previous
#include <cuda_runtime.h>

#define NB      131072
#define D       256
#define LEAVES  4
#define MID     2

constexpr int TILE_M    = 64;
constexpr int KC        = 16;
constexpr int THREADS   = 256;
constexpr int SX_STRIDE = D + 8;      // 264 floats: 16B-aligned rows

// ---------------- global scratch (no allocations allowed) ----------------
__device__ int g_idx[NB];     // expert per row
__device__ int g_perm[NB];    // rows sorted by expert
__device__ int g_hist[LEAVES];
__device__ int g_base[LEAVES];

// ---------------- main-kernel smem layout (floats) ----------------
constexpr int OFF_SX    = 0;
constexpr int OFF_SW    = OFF_SX + TILE_M * SX_STRIDE;   // 16896
constexpr int OFF_BLEAF = OFF_SW + KC * D;               // +4096
constexpr int OFF_BMID  = OFF_BLEAF + LEAVES * D;        // +1024
constexpr int OFF_BROOT = OFF_BMID + MID * D;            // +512
constexpr int OFF_ORIG  = OFF_BROOT + D;                 // +256  (64 ints)
constexpr int OFF_E     = OFF_ORIG + TILE_M;             // 64 ints
constexpr int OFF_MM    = OFF_E + TILE_M;                // 2 ints
constexpr int SMEM_FLOATS = OFF_MM + 2;
constexpr int SMEM_BYTES  = SMEM_FLOATS * (int)sizeof(float);

// ---------------- gate-kernel smem layout ----------------
constexpr int GOFF_SX  = 0;
constexpr int GOFF_WG  = GOFF_SX + TILE_M * SX_STRIDE;
constexpr int GOFF_LOG = GOFF_WG + D * LEAVES;
constexpr int GOFF_H   = GOFF_LOG + TILE_M * LEAVES;
constexpr int GATE_BYTES = (GOFF_H + LEAVES) * (int)sizeof(float);

__global__ void init_kernel() {
    if (threadIdx.x < LEAVES) g_hist[threadIdx.x] = 0;
}

// gate: per-row argmax over 4 leaf logits + global histogram
__global__ void __launch_bounds__(THREADS, 2)
gate_kernel(const float* __restrict__ x, const float* __restrict__ Wg,
            const float* __restrict__ bg)
{
    extern __shared__ float sm[];
    float* sX   = sm + GOFF_SX;
    float* sWg  = sm + GOFF_WG;
    float* sLog = sm + GOFF_LOG;
    int*   sH   = reinterpret_cast<int*>(sm + GOFF_H);

    const int tid = threadIdx.x;
    const size_t row0 = (size_t)blockIdx.x * TILE_M;

    const float4* xg = reinterpret_cast<const float4*>(x + row0 * D);
#pragma unroll
    for (int i = 0; i < (TILE_M * D / 4) / THREADS; i++) {
        int li = tid + i * THREADS;
        int r = li / (D / 4), c4 = li % (D / 4);
        float4 v = xg[r * (D / 4) + c4];
        float* dst = &sX[r * SX_STRIDE + c4 * 4];
        dst[0] = v.x; dst[1] = v.y; dst[2] = v.z; dst[3] = v.w;
    }
    for (int i = tid; i < D * LEAVES; i += THREADS) sWg[i] = Wg[i];
    if (tid < LEAVES) sH[tid] = 0;
    __syncthreads();

    {   // (row, expert) pairs: 64 x 4 = 256 threads
        int r = tid & (TILE_M - 1);
        int e = tid >> 6;
        float acc = bg[e];
        const float* xr = &sX[r * SX_STRIDE];
#pragma unroll 8
        for (int d = 0; d < D; d++) acc = fmaf(xr[d], sWg[d * LEAVES + e], acc);
        sLog[r * LEAVES + e] = acc;
    }
    __syncthreads();

    if (tid < TILE_M) {     // first-max wins (matches jnp.argmax)
        float best = sLog[tid * LEAVES];
        int bi = 0;
#pragma unroll
        for (int e = 1; e < LEAVES; e++) {
            float v = sLog[tid * LEAVES + e];
            if (v > best) { best = v; bi = e; }
        }
        g_idx[row0 + tid] = bi;
        atomicAdd(&sH[bi], 1);
    }
    __syncthreads();
    if (tid < LEAVES) atomicAdd(&g_hist[tid], sH[tid]);
}

__global__ void scan_kernel() {
    int b = 0;
    for (int e = 0; e < LEAVES; e++) { g_base[e] = b; b += g_hist[e]; }
}

// counting-sort scatter: block-aggregated atomics (4 global atomics / block)
__global__ void scatter_kernel() {
    __shared__ int cnt[LEAVES];
    __shared__ int boff[LEAVES];
    const int tid = threadIdx.x;
    const int r = blockIdx.x * blockDim.x + tid;
    if (tid < LEAVES) cnt[tid] = 0;
    __syncthreads();
    int e = g_idx[r];
    int my = atomicAdd(&cnt[e], 1);
    __syncthreads();
    if (tid < LEAVES) boff[tid] = atomicAdd(&g_base[tid], cnt[tid]);
    __syncthreads();
    g_perm[boff[e] + my] = r;
}

// One GEMM pass over K=256 (streamed through smem in KC chunks).
// a-operands loaded as float4 broadcasts (1 wavefront per 4 k-steps per row).
template <bool MASKED>
__device__ __forceinline__
void gemm_pass(const float* __restrict__ Wglob, float* sW, const float* sX,
               const float m[8], float (&acc)[8][8], int tid, int r0, int c0)
{
#pragma unroll 1
    for (int kc = 0; kc < D; kc += KC) {
        __syncthreads();   // prior chunk's consumers done before overwrite
        const float4* wg4 = reinterpret_cast<const float4*>(Wglob + (size_t)kc * D);
        float4* sW4 = reinterpret_cast<float4*>(sW);
#pragma unroll
        for (int i = 0; i < (KC * D / 4) / THREADS; i++)
            sW4[tid + i * THREADS] = wg4[tid + i * THREADS];
        __syncthreads();
#pragma unroll
        for (int k4 = 0; k4 < KC; k4 += 4) {
            float4 a4[8];
#pragma unroll
            for (int i = 0; i < 8; i++) {
                a4[i] = *reinterpret_cast<const float4*>(
                            &sX[(r0 + i) * SX_STRIDE + kc + k4]);
                if (MASKED) {
                    a4[i].x *= m[i]; a4[i].y *= m[i];
                    a4[i].z *= m[i]; a4[i].w *= m[i];
                }
            }
#pragma unroll
            for (int kk = 0; kk < 4; kk++) {
                float4 b0 = *reinterpret_cast<const float4*>(&sW[(k4 + kk) * D + c0]);
                float4 b1 = *reinterpret_cast<const float4*>(&sW[(k4 + kk) * D + c0 + 4]);
                float bb[8] = {b0.x, b0.y, b0.z, b0.w, b1.x, b1.y, b1.z, b1.w};
#pragma unroll
                for (int i = 0; i < 8; i++) {
                    float av = (kk == 0) ? a4[i].x : (kk == 1) ? a4[i].y
                             : (kk == 2) ? a4[i].z : a4[i].w;
#pragma unroll
                    for (int j = 0; j < 8; j++)
                        acc[i][j] = fmaf(av, bb[j], acc[i][j]);
                }
            }
        }
    }
}

__global__ void __launch_bounds__(THREADS, 2)
tree_kernel(const float* __restrict__ x,
            const float* __restrict__ W_leaf, const float* __restrict__ b_leaf,
            const float* __restrict__ W_mid,  const float* __restrict__ b_mid,
            const float* __restrict__ W_root, const float* __restrict__ b_root,
            float* __restrict__ out)
{
    extern __shared__ float sm[];
    float* sX   = sm + OFF_SX;
    float* sW   = sm + OFF_SW;
    float* sBlf = sm + OFF_BLEAF;
    float* sBmd = sm + OFF_BMID;
    float* sBrt = sm + OFF_BROOT;
    int* sOrig  = reinterpret_cast<int*>(sm + OFF_ORIG);
    int* sE     = reinterpret_cast<int*>(sm + OFF_E);
    int* sMM    = reinterpret_cast<int*>(sm + OFF_MM);

    const int tid = threadIdx.x;
    const size_t row0 = (size_t)blockIdx.x * TILE_M;
    const int tx = tid & 31, ty = tid >> 5;
    const int r0 = ty * 8, c0 = tx * 8;

    if (tid < TILE_M) {
        int orig = g_perm[row0 + tid];
        sOrig[tid] = orig;
        sE[tid] = g_idx[orig];
    }
    if (tid == TILE_M) { sMM[0] = LEAVES; sMM[1] = -1; }
    __syncthreads();

    // gather x rows (full-row contiguous loads, coalesced within rows)
#pragma unroll
    for (int i = 0; i < (TILE_M * D / 4) / THREADS; i++) {
        int li = tid + i * THREADS;
        int r = li / (D / 4), c4 = li % (D / 4);
        const float4* src = reinterpret_cast<const float4*>(x + (size_t)sOrig[r] * D);
        float4 v = src[c4];
        float* dst = &sX[r * SX_STRIDE + c4 * 4];
        dst[0] = v.x; dst[1] = v.y; dst[2] = v.z; dst[3] = v.w;
    }
    for (int i = tid; i < LEAVES * D; i += THREADS) sBlf[i] = b_leaf[i];
    for (int i = tid; i < MID * D;    i += THREADS) sBmd[i] = b_mid[i];
    for (int i = tid; i < D;          i += THREADS) sBrt[i] = b_root[i];
    if (tid < TILE_M) {
        atomicMin(&sMM[0], sE[tid]);
        atomicMax(&sMM[1], sE[tid]);
    }
    __syncthreads();

    const int emin = sMM[0], emax = sMM[1];

    float acc[8][8];
#pragma unroll
    for (int i = 0; i < 8; i++)
#pragma unroll
        for (int j = 0; j < 8; j++) acc[i][j] = 0.f;
    float m[8];

    // ---- leaf layer (uniform tile: single unmasked pass) ----
    if (emin == emax) {
        gemm_pass<false>(W_leaf + (size_t)emin * D * D, sW, sX, m, acc, tid, r0, c0);
    } else {
        for (int e = emin; e <= emax; e++) {
#pragma unroll
            for (int i = 0; i < 8; i++) m[i] = (sE[r0 + i] == e) ? 1.f : 0.f;
            gemm_pass<true>(W_leaf + (size_t)e * D * D, sW, sX, m, acc, tid, r0, c0);
        }
    }
    // epilogue: rows are warp-private in sX, no block sync needed here
#pragma unroll
    for (int i = 0; i < 8; i++) {
        int e = sE[r0 + i];
#pragma unroll
        for (int j = 0; j < 8; j++) {
            float v = fmaxf(acc[i][j] + sBlf[e * D + c0 + j], 0.f);
            sX[(r0 + i) * SX_STRIDE + c0 + j] = v;
            acc[i][j] = 0.f;
        }
    }

    // ---- mid layer ----
    const int pmin = emin >> 1, pmax = emax >> 1;
    if (pmin == pmax) {
        gemm_pass<false>(W_mid + (size_t)pmin * D * D, sW, sX, m, acc, tid, r0, c0);
    } else {
        for (int p = pmin; p <= pmax; p++) {
#pragma unroll
            for (int i = 0; i < 8; i++) m[i] = ((sE[r0 + i] >> 1) == p) ? 1.f : 0.f;
            gemm_pass<true>(W_mid + (size_t)p * D * D, sW, sX, m, acc, tid, r0, c0);
        }
    }
#pragma unroll
    for (int i = 0; i < 8; i++) {
        int p = sE[r0 + i] >> 1;
#pragma unroll
        for (int j = 0; j < 8; j++) {
            float v = fmaxf(acc[i][j] + sBmd[p * D + c0 + j], 0.f);
            sX[(r0 + i) * SX_STRIDE + c0 + j] = v;
            acc[i][j] = 0.f;
        }
    }

    // ---- root layer + scatter to original row positions ----
    gemm_pass<false>(W_root, sW, sX, m, acc, tid, r0, c0);
#pragma unroll
    for (int i = 0; i < 8; i++) {
        float v[8];
#pragma unroll
        for (int j = 0; j < 8; j++)
            v[j] = fmaxf(acc[i][j] + sBrt[c0 + j], 0.f);
        float4* o = reinterpret_cast<float4*>(out + (size_t)sOrig[r0 + i] * D + c0);
        o[0] = make_float4(v[0], v[1], v[2], v[3]);
        o[1] = make_float4(v[4], v[5], v[6], v[7]);
    }
}

extern "C" void kernel_launch(void* const* d_in, const int* in_sizes, int n_in,
                              void* d_out, int out_size)
{
    const float* x      = (const float*)d_in[0];
    const float* Wg     = (const float*)d_in[1];
    const float* bg     = (const float*)d_in[2];
    const float* W_leaf = (const float*)d_in[3];
    const float* b_leaf = (const float*)d_in[4];
    const float* W_mid  = (const float*)d_in[5];
    const float* b_mid  = (const float*)d_in[6];
    const float* W_root = (const float*)d_in[7];
    const float* b_root = (const float*)d_in[8];
    float* out = (float*)d_out;

    cudaFuncSetAttribute(gate_kernel,
                         cudaFuncAttributeMaxDynamicSharedMemorySize, GATE_BYTES);
    cudaFuncSetAttribute(tree_kernel,
                         cudaFuncAttributeMaxDynamicSharedMemorySize, SMEM_BYTES);

    init_kernel<<<1, 32>>>();
    gate_kernel<<<NB / TILE_M, THREADS, GATE_BYTES>>>(x, Wg, bg);
    scan_kernel<<<1, 1>>>();
    scatter_kernel<<<NB / THREADS, THREADS>>>();
    tree_kernel<<<NB / TILE_M, THREADS, SMEM_BYTES>>>(
        x, W_leaf, b_leaf, W_mid, b_mid, W_root, b_root, out);
}

// round 4
// speedup vs baseline: 2.5059x; 1.1621x over previous
#include <cuda_runtime.h>

#define NB      131072
#define D       256
#define LEAVES  4
#define MID     2

constexpr int TILE_M    = 64;
constexpr int KC        = 16;
constexpr int THREADS   = 256;
constexpr int SX_STRIDE = D + 8;      // 264 floats

typedef unsigned long long u64;
union U64F2 { u64 u; float2 f; };

// packed fp32x2 FMA (Blackwell FFMA2) — only reachable via PTX
#define FMA_F32X2(d, a, b, c) \
    asm("fma.rn.f32x2 %0, %1, %2, %3;" : "=l"(d) : "l"(a), "l"(b), "l"(c))
#define PACK2(d, x) \
    asm("mov.b64 %0, {%1, %1};" : "=l"(d) : "r"(x))

// ---------------- global scratch ----------------
__device__ int g_idx[NB];
__device__ int g_perm[NB];
__device__ int g_hist[LEAVES];
__device__ int g_base[LEAVES];

// ---------------- main-kernel smem layout (floats) ----------------
constexpr int OFF_SX    = 0;
constexpr int OFF_SW    = OFF_SX + TILE_M * SX_STRIDE;
constexpr int OFF_BLEAF = OFF_SW + KC * D;
constexpr int OFF_BMID  = OFF_BLEAF + LEAVES * D;
constexpr int OFF_BROOT = OFF_BMID + MID * D;
constexpr int OFF_ORIG  = OFF_BROOT + D;
constexpr int OFF_E     = OFF_ORIG + TILE_M;
constexpr int OFF_MM    = OFF_E + TILE_M;
constexpr int SMEM_FLOATS = OFF_MM + 2;
constexpr int SMEM_BYTES  = SMEM_FLOATS * (int)sizeof(float);

// ---------------- gate-kernel smem layout ----------------
constexpr int GOFF_SX  = 0;
constexpr int GOFF_WG  = GOFF_SX + TILE_M * SX_STRIDE;
constexpr int GOFF_LOG = GOFF_WG + D * LEAVES;
constexpr int GOFF_H   = GOFF_LOG + TILE_M * LEAVES;
constexpr int GATE_BYTES = (GOFF_H + LEAVES) * (int)sizeof(float);

__global__ void init_kernel() {
    if (threadIdx.x < LEAVES) g_hist[threadIdx.x] = 0;
}

__global__ void __launch_bounds__(THREADS, 2)
gate_kernel(const float* __restrict__ x, const float* __restrict__ Wg,
            const float* __restrict__ bg)
{
    extern __shared__ float sm[];
    float* sX   = sm + GOFF_SX;
    float* sWg  = sm + GOFF_WG;
    float* sLog = sm + GOFF_LOG;
    int*   sH   = reinterpret_cast<int*>(sm + GOFF_H);

    const int tid = threadIdx.x;
    const size_t row0 = (size_t)blockIdx.x * TILE_M;

    const float4* xg = reinterpret_cast<const float4*>(x + row0 * D);
#pragma unroll
    for (int i = 0; i < (TILE_M * D / 4) / THREADS; i++) {
        int li = tid + i * THREADS;
        int r = li / (D / 4), c4 = li % (D / 4);
        float4 v = xg[r * (D / 4) + c4];
        float* dst = &sX[r * SX_STRIDE + c4 * 4];
        dst[0] = v.x; dst[1] = v.y; dst[2] = v.z; dst[3] = v.w;
    }
    for (int i = tid; i < D * LEAVES; i += THREADS) sWg[i] = Wg[i];
    if (tid < LEAVES) sH[tid] = 0;
    __syncthreads();

    {
        int r = tid & (TILE_M - 1);
        int e = tid >> 6;
        float acc = bg[e];
        const float* xr = &sX[r * SX_STRIDE];
#pragma unroll 8
        for (int d = 0; d < D; d++) acc = fmaf(xr[d], sWg[d * LEAVES + e], acc);
        sLog[r * LEAVES + e] = acc;
    }
    __syncthreads();

    if (tid < TILE_M) {     // first-max wins (matches jnp.argmax)
        float best = sLog[tid * LEAVES];
        int bi = 0;
#pragma unroll
        for (int e = 1; e < LEAVES; e++) {
            float v = sLog[tid * LEAVES + e];
            if (v > best) { best = v; bi = e; }
        }
        g_idx[row0 + tid] = bi;
        atomicAdd(&sH[bi], 1);
    }
    __syncthreads();
    if (tid < LEAVES) atomicAdd(&g_hist[tid], sH[tid]);
}

__global__ void scan_kernel() {
    int b = 0;
    for (int e = 0; e < LEAVES; e++) { g_base[e] = b; b += g_hist[e]; }
}

__global__ void scatter_kernel() {
    __shared__ int cnt[LEAVES];
    __shared__ int boff[LEAVES];
    const int tid = threadIdx.x;
    const int r = blockIdx.x * blockDim.x + tid;
    if (tid < LEAVES) cnt[tid] = 0;
    __syncthreads();
    int e = g_idx[r];
    int my = atomicAdd(&cnt[e], 1);
    __syncthreads();
    if (tid < LEAVES) boff[tid] = atomicAdd(&g_base[tid], cnt[tid]);
    __syncthreads();
    g_perm[boff[e] + my] = r;
}

// GEMM pass, packed f32x2 accumulators: acc2[8][4] holds 8x8 fp32 outputs.
template <bool MASKED>
__device__ __forceinline__
void gemm_pass(const float* __restrict__ Wglob, float* sW, const float* sX,
               const float m[8], u64 (&acc2)[8][4], int tid, int r0, int c0)
{
#pragma unroll 1
    for (int kc = 0; kc < D; kc += KC) {
        __syncthreads();
        const float4* wg4 = reinterpret_cast<const float4*>(Wglob + (size_t)kc * D);
        float4* sW4 = reinterpret_cast<float4*>(sW);
#pragma unroll
        for (int i = 0; i < (KC * D / 4) / THREADS; i++)
            sW4[tid + i * THREADS] = wg4[tid + i * THREADS];
        __syncthreads();
#pragma unroll
        for (int k4 = 0; k4 < KC; k4 += 4) {
            float4 a4[8];
#pragma unroll
            for (int i = 0; i < 8; i++) {
                a4[i] = *reinterpret_cast<const float4*>(
                            &sX[(r0 + i) * SX_STRIDE + kc + k4]);
                if (MASKED) {
                    a4[i].x *= m[i]; a4[i].y *= m[i];
                    a4[i].z *= m[i]; a4[i].w *= m[i];
                }
            }
#pragma unroll
            for (int kk = 0; kk < 4; kk++) {
                const ulonglong2* bp = reinterpret_cast<const ulonglong2*>(
                                           &sW[(k4 + kk) * D + c0]);
                ulonglong2 b01 = bp[0];
                ulonglong2 b23 = bp[1];
#pragma unroll
                for (int i = 0; i < 8; i++) {
                    float av = (kk == 0) ? a4[i].x : (kk == 1) ? a4[i].y
                             : (kk == 2) ? a4[i].z : a4[i].w;
                    u64 a2;
                    PACK2(a2, __float_as_uint(av));
                    FMA_F32X2(acc2[i][0], a2, b01.x, acc2[i][0]);
                    FMA_F32X2(acc2[i][1], a2, b01.y, acc2[i][1]);
                    FMA_F32X2(acc2[i][2], a2, b23.x, acc2[i][2]);
                    FMA_F32X2(acc2[i][3], a2, b23.y, acc2[i][3]);
                }
            }
        }
    }
}

__global__ void __launch_bounds__(THREADS, 2)
tree_kernel(const float* __restrict__ x,
            const float* __restrict__ W_leaf, const float* __restrict__ b_leaf,
            const float* __restrict__ W_mid,  const float* __restrict__ b_mid,
            const float* __restrict__ W_root, const float* __restrict__ b_root,
            float* __restrict__ out)
{
    extern __shared__ float sm[];
    float* sX   = sm + OFF_SX;
    float* sW   = sm + OFF_SW;
    float* sBlf = sm + OFF_BLEAF;
    float* sBmd = sm + OFF_BMID;
    float* sBrt = sm + OFF_BROOT;
    int* sOrig  = reinterpret_cast<int*>(sm + OFF_ORIG);
    int* sE     = reinterpret_cast<int*>(sm + OFF_E);
    int* sMM    = reinterpret_cast<int*>(sm + OFF_MM);

    const int tid = threadIdx.x;
    const size_t row0 = (size_t)blockIdx.x * TILE_M;
    const int tx = tid & 31, ty = tid >> 5;
    const int r0 = ty * 8, c0 = tx * 8;

    if (tid < TILE_M) {
        int orig = g_perm[row0 + tid];
        sOrig[tid] = orig;
        sE[tid] = g_idx[orig];
    }
    if (tid == TILE_M) { sMM[0] = LEAVES; sMM[1] = -1; }
    __syncthreads();

#pragma unroll
    for (int i = 0; i < (TILE_M * D / 4) / THREADS; i++) {
        int li = tid + i * THREADS;
        int r = li / (D / 4), c4 = li % (D / 4);
        const float4* src = reinterpret_cast<const float4*>(x + (size_t)sOrig[r] * D);
        float4 v = src[c4];
        float* dst = &sX[r * SX_STRIDE + c4 * 4];
        dst[0] = v.x; dst[1] = v.y; dst[2] = v.z; dst[3] = v.w;
    }
    for (int i = tid; i < LEAVES * D; i += THREADS) sBlf[i] = b_leaf[i];
    for (int i = tid; i < MID * D;    i += THREADS) sBmd[i] = b_mid[i];
    for (int i = tid; i < D;          i += THREADS) sBrt[i] = b_root[i];
    if (tid < TILE_M) {
        atomicMin(&sMM[0], sE[tid]);
        atomicMax(&sMM[1], sE[tid]);
    }
    __syncthreads();

    const int emin = sMM[0], emax = sMM[1];

    u64 acc2[8][4];
#pragma unroll
    for (int i = 0; i < 8; i++)
#pragma unroll
        for (int j = 0; j < 4; j++) acc2[i][j] = 0ull;   // {0.f, 0.f}
    float m[8];

    // ---- leaf layer ----
    if (emin == emax) {
        gemm_pass<false>(W_leaf + (size_t)emin * D * D, sW, sX, m, acc2, tid, r0, c0);
    } else {
        for (int e = emin; e <= emax; e++) {
#pragma unroll
            for (int i = 0; i < 8; i++) m[i] = (sE[r0 + i] == e) ? 1.f : 0.f;
            gemm_pass<true>(W_leaf + (size_t)e * D * D, sW, sX, m, acc2, tid, r0, c0);
        }
    }
#pragma unroll
    for (int i = 0; i < 8; i++) {
        int e = sE[r0 + i];
#pragma unroll
        for (int p = 0; p < 4; p++) {
            U64F2 u; u.u = acc2[i][p];
            float v0 = fmaxf(u.f.x + sBlf[e * D + c0 + 2 * p],     0.f);
            float v1 = fmaxf(u.f.y + sBlf[e * D + c0 + 2 * p + 1], 0.f);
            sX[(r0 + i) * SX_STRIDE + c0 + 2 * p]     = v0;
            sX[(r0 + i) * SX_STRIDE + c0 + 2 * p + 1] = v1;
            acc2[i][p] = 0ull;
        }
    }

    // ---- mid layer ----
    const int pmin = emin >> 1, pmax = emax >> 1;
    if (pmin == pmax) {
        gemm_pass<false>(W_mid + (size_t)pmin * D * D, sW, sX, m, acc2, tid, r0, c0);
    } else {
        for (int p = pmin; p <= pmax; p++) {
#pragma unroll
            for (int i = 0; i < 8; i++) m[i] = ((sE[r0 + i] >> 1) == p) ? 1.f : 0.f;
            gemm_pass<true>(W_mid + (size_t)p * D * D, sW, sX, m, acc2, tid, r0, c0);
        }
    }
#pragma unroll
    for (int i = 0; i < 8; i++) {
        int pp = sE[r0 + i] >> 1;
#pragma unroll
        for (int p = 0; p < 4; p++) {
            U64F2 u; u.u = acc2[i][p];
            float v0 = fmaxf(u.f.x + sBmd[pp * D + c0 + 2 * p],     0.f);
            float v1 = fmaxf(u.f.y + sBmd[pp * D + c0 + 2 * p + 1], 0.f);
            sX[(r0 + i) * SX_STRIDE + c0 + 2 * p]     = v0;
            sX[(r0 + i) * SX_STRIDE + c0 + 2 * p + 1] = v1;
            acc2[i][p] = 0ull;
        }
    }

    // ---- root layer + scatter ----
    gemm_pass<false>(W_root, sW, sX, m, acc2, tid, r0, c0);
#pragma unroll
    for (int i = 0; i < 8; i++) {
        float v[8];
#pragma unroll
        for (int p = 0; p < 4; p++) {
            U64F2 u; u.u = acc2[i][p];
            v[2 * p]     = fmaxf(u.f.x + sBrt[c0 + 2 * p],     0.f);
            v[2 * p + 1] = fmaxf(u.f.y + sBrt[c0 + 2 * p + 1], 0.f);
        }
        float4* o = reinterpret_cast<float4*>(out + (size_t)sOrig[r0 + i] * D + c0);
        o[0] = make_float4(v[0], v[1], v[2], v[3]);
        o[1] = make_float4(v[4], v[5], v[6], v[7]);
    }
}

extern "C" void kernel_launch(void* const* d_in, const int* in_sizes, int n_in,
                              void* d_out, int out_size)
{
    const float* x      = (const float*)d_in[0];
    const float* Wg     = (const float*)d_in[1];
    const float* bg     = (const float*)d_in[2];
    const float* W_leaf = (const float*)d_in[3];
    const float* b_leaf = (const float*)d_in[4];
    const float* W_mid  = (const float*)d_in[5];
    const float* b_mid  = (const float*)d_in[6];
    const float* W_root = (const float*)d_in[7];
    const float* b_root = (const float*)d_in[8];
    float* out = (float*)d_out;

    cudaFuncSetAttribute(gate_kernel,
                         cudaFuncAttributeMaxDynamicSharedMemorySize, GATE_BYTES);
    cudaFuncSetAttribute(tree_kernel,
                         cudaFuncAttributeMaxDynamicSharedMemorySize, SMEM_BYTES);

    init_kernel<<<1, 32>>>();
    gate_kernel<<<NB / TILE_M, THREADS, GATE_BYTES>>>(x, Wg, bg);
    scan_kernel<<<1, 1>>>();
    scatter_kernel<<<NB / THREADS, THREADS>>>();
    tree_kernel<<<NB / TILE_M, THREADS, SMEM_BYTES>>>(
        x, W_leaf, b_leaf, W_mid, b_mid, W_root, b_root, out);
}

// round 6
// speedup vs baseline: 3.4403x; 1.3729x over previous
#include <cuda_runtime.h>
#include <cuda_bf16.h>
#include <cstdint>

#define NB      131072
#define D       256
#define LEAVES  4
#define MID     2

typedef unsigned long long u64;
union U64F2 { u64 u; float2 f; };

__device__ __forceinline__ uint32_t pack_bf2(__nv_bfloat16 a, __nv_bfloat16 b) {
    __nv_bfloat162 p = __halves2bfloat162(a, b);
    return *reinterpret_cast<uint32_t*>(&p);
}

// portable HMMA: m16n8k16 row.col f32.bf16.bf16.f32
__device__ __forceinline__
void mma_bf16(float* c, uint32_t a0, uint32_t a1, uint32_t a2, uint32_t a3,
              uint32_t b0, uint32_t b1)
{
    asm("mma.sync.aligned.m16n8k16.row.col.f32.bf16.bf16.f32 "
        "{%0,%1,%2,%3}, {%4,%5,%6,%7}, {%8,%9}, {%0,%1,%2,%3};"
        : "+f"(c[0]), "+f"(c[1]), "+f"(c[2]), "+f"(c[3])
        : "r"(a0), "r"(a1), "r"(a2), "r"(a3), "r"(b0), "r"(b1));
}

// ======================= global scratch =======================
__device__ int g_idx[NB];
__device__ int g_perm[NB];
__device__ int g_hist[LEAVES];
__device__ int g_base[LEAVES];
// 7 mats x [hi|lo plane] x [n=256][k=256] bf16  (B col-major for mma.sync)
__device__ __align__(16) unsigned short g_wimg[7 * 2 * 65536];

// ======================= gate / sort =======================
constexpr int GTILE = 64;
constexpr int GSTR  = D + 8;
constexpr int GOFF_SX  = 0;
constexpr int GOFF_WG  = GOFF_SX + GTILE * GSTR;
constexpr int GOFF_LOG = GOFF_WG + D * LEAVES;
constexpr int GOFF_H   = GOFF_LOG + GTILE * LEAVES;
constexpr int GATE_BYTES = (GOFF_H + LEAVES) * (int)sizeof(float);

__global__ void init_kernel() {
    if (threadIdx.x < LEAVES) g_hist[threadIdx.x] = 0;
}

__global__ void __launch_bounds__(256, 2)
gate_kernel(const float* __restrict__ x, const float* __restrict__ Wg,
            const float* __restrict__ bg)
{
    extern __shared__ float sm[];
    float* sX = sm + GOFF_SX;  float* sWg = sm + GOFF_WG;
    float* sLog = sm + GOFF_LOG;
    int* sH = reinterpret_cast<int*>(sm + GOFF_H);
    const int tid = threadIdx.x;
    const size_t row0 = (size_t)blockIdx.x * GTILE;

    const float4* xg = reinterpret_cast<const float4*>(x + row0 * D);
#pragma unroll
    for (int i = 0; i < (GTILE * D / 4) / 256; i++) {
        int li = tid + i * 256;
        int r = li / (D / 4), c4 = li % (D / 4);
        float4 v = xg[r * (D / 4) + c4];
        float* dst = &sX[r * GSTR + c4 * 4];
        dst[0] = v.x; dst[1] = v.y; dst[2] = v.z; dst[3] = v.w;
    }
    for (int i = tid; i < D * LEAVES; i += 256) sWg[i] = Wg[i];
    if (tid < LEAVES) sH[tid] = 0;
    __syncthreads();
    {
        int r = tid & (GTILE - 1);
        int e = tid >> 6;
        float acc = bg[e];
        const float* xr = &sX[r * GSTR];
#pragma unroll 8
        for (int d = 0; d < D; d++) acc = fmaf(xr[d], sWg[d * LEAVES + e], acc);
        sLog[r * LEAVES + e] = acc;
    }
    __syncthreads();
    if (tid < GTILE) {
        float best = sLog[tid * LEAVES];
        int bi = 0;
#pragma unroll
        for (int e = 1; e < LEAVES; e++) {
            float v = sLog[tid * LEAVES + e];
            if (v > best) { best = v; bi = e; }
        }
        g_idx[row0 + tid] = bi;
        atomicAdd(&sH[bi], 1);
    }
    __syncthreads();
    if (tid < LEAVES) atomicAdd(&g_hist[tid], sH[tid]);
}

__global__ void scan_kernel() {
    int b = 0;
    for (int e = 0; e < LEAVES; e++) { g_base[e] = b; b += g_hist[e]; }
}

__global__ void scatter_kernel() {
    __shared__ int cnt[LEAVES];
    __shared__ int boff[LEAVES];
    const int tid = threadIdx.x;
    const int r = blockIdx.x * blockDim.x + tid;
    if (tid < LEAVES) cnt[tid] = 0;
    __syncthreads();
    int e = g_idx[r];
    int my = atomicAdd(&cnt[e], 1);
    __syncthreads();
    if (tid < LEAVES) boff[tid] = atomicAdd(&g_base[tid], cnt[tid]);
    __syncthreads();
    g_perm[boff[e] + my] = r;
}

// ======== weight prep: fp32 W[k][n] -> bf16 hi/lo images img[n][k] ========
__global__ void prep_w_kernel(const float* __restrict__ Wl,
                              const float* __restrict__ Wm,
                              const float* __restrict__ Wr)
{
    int gid = blockIdx.x * 256 + threadIdx.x;      // 7*65536 total
    int mat = gid >> 16;
    int rem = gid & 0xFFFF;
    int n = rem >> 8, k = rem & 255;
    float v;
    if (mat < 4)      v = Wl[mat * 65536 + k * 256 + n];
    else if (mat < 6) v = Wm[(mat - 4) * 65536 + k * 256 + n];
    else              v = Wr[k * 256 + n];
    __nv_bfloat16 h = __float2bfloat16(v);
    float lof = v - __bfloat162float(h);
    __nv_bfloat16 l = __float2bfloat16(lof);
    unsigned short* base = g_wimg + (size_t)mat * 131072;
    base[n * 256 + k]         = __bfloat16_as_ushort(h);
    base[65536 + n * 256 + k] = __bfloat16_as_ushort(l);
}

// ======================= main mma.sync kernel =======================
// smem bytes:
//   A_hi plane [128][264 bf16]  67584
//   A_lo plane                  67584   (offset 67584)
//   B double buffer: 2 x (2 planes x 256 x 40 bf16) = 2 x 40960 (offset 135168)
//   bias 3*256 f32  (offset 217088)
//   sOrig 128 ints  (offset 220160)
constexpr int A_STR_B   = 264 * 2;                 // 528
constexpr int OFF_AHI   = 0;
constexpr int OFF_ALO   = 67584;
constexpr int OFF_B     = 135168;
constexpr int B_PLANE_B = 256 * 40 * 2;            // 20480
constexpr int B_BUF_B   = 2 * B_PLANE_B;           // 40960
constexpr int OFF_BIAS  = OFF_B + 2 * B_BUF_B;     // 217088
constexpr int OFF_ORIG  = OFF_BIAS + 768 * 4;      // 220160
constexpr int MMA_SMEM  = OFF_ORIG + 512;          // 220672

__global__ void __launch_bounds__(512, 1)
tree_mma_kernel(const float* __restrict__ x,
                const float* __restrict__ b_leaf,
                const float* __restrict__ b_mid,
                const float* __restrict__ b_root,
                float* __restrict__ out)
{
    extern __shared__ char smc[];
    int* sOrig = reinterpret_cast<int*>(smc + OFF_ORIG);
    float* sBias = reinterpret_cast<float*>(smc + OFF_BIAS);

    const int tid = threadIdx.x;
    const int lane = tid & 31, w = tid >> 5;
    const int wm = w & 3, wn = w >> 2;           // 4 x 4 warp grid
    const int g = lane >> 2, tg = lane & 3;
    const size_t row0 = (size_t)blockIdx.x * 128;

    if (tid < 128) sOrig[tid] = g_perm[row0 + tid];
    __syncthreads();
    const int eL = g_idx[sOrig[0]];
    if (eL != g_idx[sOrig[127]]) return;          // mixed tile -> fallback
    const int eM = eL >> 1;
    const int matIdx[3] = { eL, 4 + eM, 6 };

    for (int i = tid; i < 256; i += 512) {
        sBias[i]       = b_leaf[eL * 256 + i];
        sBias[256 + i] = b_mid[eM * 256 + i];
        sBias[512 + i] = b_root[i];
    }

    // ---- A init: thread -> (row tid>>2, 64-col segment tid&3), split hi/lo ----
    {
        int r = tid >> 2, seg = tid & 3;
        const float4* xr = reinterpret_cast<const float4*>(
                               x + (size_t)sOrig[r] * D) + seg * 16;
        char* aH = smc + OFF_AHI + r * A_STR_B + seg * 128;
        char* aL = smc + OFF_ALO + r * A_STR_B + seg * 128;
#pragma unroll
        for (int i = 0; i < 16; i++) {
            float4 f = xr[i];
            __nv_bfloat16 h0 = __float2bfloat16(f.x), h1 = __float2bfloat16(f.y);
            __nv_bfloat16 h2 = __float2bfloat16(f.z), h3 = __float2bfloat16(f.w);
            uint2 hv, lv;
            hv.x = pack_bf2(h0, h1);
            hv.y = pack_bf2(h2, h3);
            lv.x = pack_bf2(__float2bfloat16(f.x - __bfloat162float(h0)),
                            __float2bfloat16(f.y - __bfloat162float(h1)));
            lv.y = pack_bf2(__float2bfloat16(f.z - __bfloat162float(h2)),
                            __float2bfloat16(f.w - __bfloat162float(h3)));
            *reinterpret_cast<uint2*>(aH + i * 8) = hv;
            *reinterpret_cast<uint2*>(aL + i * 8) = lv;
        }
    }

    // ---- stage B chunk 0 of layer 0 into buffer 0 ----
    {
        int p = tid >> 8, n = tid & 255;
        const uint4* src = reinterpret_cast<const uint4*>(
            g_wimg + (size_t)matIdx[0] * 131072 + p * 65536 + n * 256);
        uint4* dst = reinterpret_cast<uint4*>(
            smc + OFF_B + p * B_PLANE_B + n * 80);
        dst[0] = src[0]; dst[1] = src[1]; dst[2] = src[2]; dst[3] = src[3];
    }
    __syncthreads();

    float acc[2][8][4];
#pragma unroll
    for (int mt = 0; mt < 2; mt++)
#pragma unroll
        for (int nt = 0; nt < 8; nt++)
#pragma unroll
            for (int q = 0; q < 4; q++) acc[mt][nt][q] = 0.f;

    int cur = 0;
    const int pfp = tid >> 8, pfn = tid & 255;     // B staging coords

#pragma unroll 1
    for (int l = 0; l < 3; l++) {
#pragma unroll 1
        for (int kc = 0; kc < 8; kc++) {
            // prefetch next chunk (next layer's chunk 0 at boundaries)
            bool hasNext = (kc < 7) || (l < 2);
            uint4 pf0, pf1, pf2, pf3;
            if (hasNext) {
                int nl  = (kc < 7) ? l : l + 1;
                int nkc = (kc < 7) ? kc + 1 : 0;
                const uint4* src = reinterpret_cast<const uint4*>(
                    g_wimg + (size_t)matIdx[nl] * 131072 + pfp * 65536
                    + pfn * 256 + nkc * 32);
                pf0 = src[0]; pf1 = src[1]; pf2 = src[2]; pf3 = src[3];
            }

            // ---- compute 2 k16-steps on buffer `cur` ----
            const char* bBase = smc + OFF_B + cur * B_BUF_B;
#pragma unroll
            for (int kk = 0; kk < 2; kk++) {
                const int k = kc * 32 + kk * 16;
                uint32_t aH[2][4], aL[2][4];
#pragma unroll
                for (int mt = 0; mt < 2; mt++) {
                    const char* pa = smc + OFF_AHI
                        + (wm * 32 + mt * 16 + g) * A_STR_B + (k + tg * 2) * 2;
                    aH[mt][0] = *reinterpret_cast<const uint32_t*>(pa);
                    aH[mt][1] = *reinterpret_cast<const uint32_t*>(pa + 8 * A_STR_B);
                    aH[mt][2] = *reinterpret_cast<const uint32_t*>(pa + 16);
                    aH[mt][3] = *reinterpret_cast<const uint32_t*>(pa + 8 * A_STR_B + 16);
                    const char* pl = pa + OFF_ALO;
                    aL[mt][0] = *reinterpret_cast<const uint32_t*>(pl);
                    aL[mt][1] = *reinterpret_cast<const uint32_t*>(pl + 8 * A_STR_B);
                    aL[mt][2] = *reinterpret_cast<const uint32_t*>(pl + 16);
                    aL[mt][3] = *reinterpret_cast<const uint32_t*>(pl + 8 * A_STR_B + 16);
                }
#pragma unroll
                for (int nt = 0; nt < 8; nt++) {
                    const char* pb = bBase + (wn * 64 + nt * 8 + g) * 80
                                     + (kk * 16 + tg * 2) * 2;
                    uint32_t bh0 = *reinterpret_cast<const uint32_t*>(pb);
                    uint32_t bh1 = *reinterpret_cast<const uint32_t*>(pb + 16);
                    uint32_t bl0 = *reinterpret_cast<const uint32_t*>(pb + B_PLANE_B);
                    uint32_t bl1 = *reinterpret_cast<const uint32_t*>(pb + B_PLANE_B + 16);
#pragma unroll
                    for (int mt = 0; mt < 2; mt++) {
                        mma_bf16(acc[mt][nt], aH[mt][0], aH[mt][1], aH[mt][2], aH[mt][3], bh0, bh1);
                        mma_bf16(acc[mt][nt], aL[mt][0], aL[mt][1], aL[mt][2], aL[mt][3], bh0, bh1);
                        mma_bf16(acc[mt][nt], aH[mt][0], aH[mt][1], aH[mt][2], aH[mt][3], bl0, bl1);
                    }
                }
            }

            if (hasNext) {
                uint4* dst = reinterpret_cast<uint4*>(
                    smc + OFF_B + (cur ^ 1) * B_BUF_B + pfp * B_PLANE_B + pfn * 80);
                dst[0] = pf0; dst[1] = pf1; dst[2] = pf2; dst[3] = pf3;
            }
            __syncthreads();
            cur ^= 1;
        }

        // ---- epilogue ----
        const float* sB = sBias + l * 256;
        if (l < 2) {
            // bias + relu + hi/lo split back into A planes
#pragma unroll
            for (int mt = 0; mt < 2; mt++) {
#pragma unroll
                for (int nt = 0; nt < 8; nt++) {
                    int col = wn * 64 + nt * 8 + tg * 2;
                    float b0 = sB[col], b1 = sB[col + 1];
                    int rlo = wm * 32 + mt * 16 + g;
#pragma unroll
                    for (int half = 0; half < 2; half++) {
                        int r = rlo + half * 8;
                        float v0 = fmaxf(acc[mt][nt][2 * half]     + b0, 0.f);
                        float v1 = fmaxf(acc[mt][nt][2 * half + 1] + b1, 0.f);
                        __nv_bfloat16 h0 = __float2bfloat16(v0);
                        __nv_bfloat16 h1 = __float2bfloat16(v1);
                        uint32_t hv = pack_bf2(h0, h1);
                        uint32_t lv = pack_bf2(
                            __float2bfloat16(v0 - __bfloat162float(h0)),
                            __float2bfloat16(v1 - __bfloat162float(h1)));
                        char* pa = smc + OFF_AHI + r * A_STR_B + col * 2;
                        *reinterpret_cast<uint32_t*>(pa) = hv;
                        *reinterpret_cast<uint32_t*>(pa + OFF_ALO) = lv;
                        acc[mt][nt][2 * half] = 0.f;
                        acc[mt][nt][2 * half + 1] = 0.f;
                    }
                }
            }
            __syncthreads();
        } else {
            // bias + relu + scatter to original rows
#pragma unroll
            for (int mt = 0; mt < 2; mt++) {
#pragma unroll
                for (int half = 0; half < 2; half++) {
                    int r = wm * 32 + mt * 16 + g + half * 8;
                    float* orow = out + (size_t)sOrig[r] * D;
#pragma unroll
                    for (int nt = 0; nt < 8; nt++) {
                        int col = wn * 64 + nt * 8 + tg * 2;
                        float2 v;
                        v.x = fmaxf(acc[mt][nt][2 * half]     + sB[col],     0.f);
                        v.y = fmaxf(acc[mt][nt][2 * half + 1] + sB[col + 1], 0.f);
                        *reinterpret_cast<float2*>(orow + col) = v;
                    }
                }
            }
        }
    }
}

// ======================= FFMA2 fallback for mixed 128-tiles =======================
constexpr int FTILE = 64;
constexpr int FKC = 16;
constexpr int FSTR = D + 8;
constexpr int FOFF_SX = 0;
constexpr int FOFF_SW = FOFF_SX + FTILE * FSTR;
constexpr int FOFF_BLEAF = FOFF_SW + FKC * D;
constexpr int FOFF_BMID = FOFF_BLEAF + LEAVES * D;
constexpr int FOFF_BROOT = FOFF_BMID + MID * D;
constexpr int FOFF_ORIG = FOFF_BROOT + D;
constexpr int FOFF_E = FOFF_ORIG + FTILE;
constexpr int FOFF_MM = FOFF_E + FTILE;
constexpr int FB_BYTES = (FOFF_MM + 2) * (int)sizeof(float);

#define FMA_F32X2(d, a, b, c) \
    asm("fma.rn.f32x2 %0, %1, %2, %3;" : "=l"(d) : "l"(a), "l"(b), "l"(c))
#define PACK2(d, xx) \
    asm("mov.b64 %0, {%1, %1};" : "=l"(d) : "r"(xx))

template <bool MASKED>
__device__ __forceinline__
void fb_gemm(const float* __restrict__ Wglob, float* sW, const float* sX,
             const float m[8], u64 (&acc2)[8][4], int tid, int r0, int c0)
{
#pragma unroll 1
    for (int kc = 0; kc < D; kc += FKC) {
        __syncthreads();
        const float4* wg4 = reinterpret_cast<const float4*>(Wglob + (size_t)kc * D);
        float4* sW4 = reinterpret_cast<float4*>(sW);
#pragma unroll
        for (int i = 0; i < (FKC * D / 4) / 256; i++)
            sW4[tid + i * 256] = wg4[tid + i * 256];
        __syncthreads();
#pragma unroll
        for (int k4 = 0; k4 < FKC; k4 += 4) {
            float4 a4[8];
#pragma unroll
            for (int i = 0; i < 8; i++) {
                a4[i] = *reinterpret_cast<const float4*>(&sX[(r0 + i) * FSTR + kc + k4]);
                if (MASKED) {
                    a4[i].x *= m[i]; a4[i].y *= m[i];
                    a4[i].z *= m[i]; a4[i].w *= m[i];
                }
            }
#pragma unroll
            for (int kk = 0; kk < 4; kk++) {
                const ulonglong2* bp =
                    reinterpret_cast<const ulonglong2*>(&sW[(k4 + kk) * D + c0]);
                ulonglong2 b01 = bp[0];
                ulonglong2 b23 = bp[1];
#pragma unroll
                for (int i = 0; i < 8; i++) {
                    float av = (kk == 0) ? a4[i].x : (kk == 1) ? a4[i].y
                             : (kk == 2) ? a4[i].z : a4[i].w;
                    u64 a2;
                    PACK2(a2, __float_as_uint(av));
                    FMA_F32X2(acc2[i][0], a2, b01.x, acc2[i][0]);
                    FMA_F32X2(acc2[i][1], a2, b01.y, acc2[i][1]);
                    FMA_F32X2(acc2[i][2], a2, b23.x, acc2[i][2]);
                    FMA_F32X2(acc2[i][3], a2, b23.y, acc2[i][3]);
                }
            }
        }
    }
}

__global__ void __launch_bounds__(256, 2)
fallback_kernel(const float* __restrict__ x,
                const float* __restrict__ W_leaf, const float* __restrict__ b_leaf,
                const float* __restrict__ W_mid,  const float* __restrict__ b_mid,
                const float* __restrict__ W_root, const float* __restrict__ b_root,
                float* __restrict__ out)
{
    // only process 64-tiles whose containing 128-tile is expert-mixed
    const size_t t128 = (size_t)(blockIdx.x >> 1) * 128;
    if (g_idx[g_perm[t128]] == g_idx[g_perm[t128 + 127]]) return;

    extern __shared__ float sm[];
    float* sX = sm + FOFF_SX;  float* sW = sm + FOFF_SW;
    float* sBlf = sm + FOFF_BLEAF;  float* sBmd = sm + FOFF_BMID;
    float* sBrt = sm + FOFF_BROOT;
    int* sOrig = reinterpret_cast<int*>(sm + FOFF_ORIG);
    int* sE = reinterpret_cast<int*>(sm + FOFF_E);
    int* sMM = reinterpret_cast<int*>(sm + FOFF_MM);

    const int tid = threadIdx.x;
    const size_t row0 = (size_t)blockIdx.x * FTILE;
    const int tx = tid & 31, ty = tid >> 5;
    const int r0 = ty * 8, c0 = tx * 8;

    if (tid < FTILE) {
        int orig = g_perm[row0 + tid];
        sOrig[tid] = orig;
        sE[tid] = g_idx[orig];
    }
    if (tid == FTILE) { sMM[0] = LEAVES; sMM[1] = -1; }
    __syncthreads();

#pragma unroll
    for (int i = 0; i < (FTILE * D / 4) / 256; i++) {
        int li = tid + i * 256;
        int r = li / (D / 4), c4 = li % (D / 4);
        const float4* src = reinterpret_cast<const float4*>(x + (size_t)sOrig[r] * D);
        float4 v = src[c4];
        float* dst = &sX[r * FSTR + c4 * 4];
        dst[0] = v.x; dst[1] = v.y; dst[2] = v.z; dst[3] = v.w;
    }
    for (int i = tid; i < LEAVES * D; i += 256) sBlf[i] = b_leaf[i];
    for (int i = tid; i < MID * D;    i += 256) sBmd[i] = b_mid[i];
    for (int i = tid; i < D;          i += 256) sBrt[i] = b_root[i];
    if (tid < FTILE) {
        atomicMin(&sMM[0], sE[tid]);
        atomicMax(&sMM[1], sE[tid]);
    }
    __syncthreads();

    const int emin = sMM[0], emax = sMM[1];
    u64 acc2[8][4];
#pragma unroll
    for (int i = 0; i < 8; i++)
#pragma unroll
        for (int j = 0; j < 4; j++) acc2[i][j] = 0ull;
    float m[8];

    if (emin == emax) {
        fb_gemm<false>(W_leaf + (size_t)emin * D * D, sW, sX, m, acc2, tid, r0, c0);
    } else {
        for (int e = emin; e <= emax; e++) {
#pragma unroll
            for (int i = 0; i < 8; i++) m[i] = (sE[r0 + i] == e) ? 1.f : 0.f;
            fb_gemm<true>(W_leaf + (size_t)e * D * D, sW, sX, m, acc2, tid, r0, c0);
        }
    }
#pragma unroll
    for (int i = 0; i < 8; i++) {
        int e = sE[r0 + i];
#pragma unroll
        for (int p = 0; p < 4; p++) {
            U64F2 u; u.u = acc2[i][p];
            sX[(r0 + i) * FSTR + c0 + 2 * p]     = fmaxf(u.f.x + sBlf[e * D + c0 + 2 * p], 0.f);
            sX[(r0 + i) * FSTR + c0 + 2 * p + 1] = fmaxf(u.f.y + sBlf[e * D + c0 + 2 * p + 1], 0.f);
            acc2[i][p] = 0ull;
        }
    }

    const int pmin = emin >> 1, pmax = emax >> 1;
    if (pmin == pmax) {
        fb_gemm<false>(W_mid + (size_t)pmin * D * D, sW, sX, m, acc2, tid, r0, c0);
    } else {
        for (int p = pmin; p <= pmax; p++) {
#pragma unroll
            for (int i = 0; i < 8; i++) m[i] = ((sE[r0 + i] >> 1) == p) ? 1.f : 0.f;
            fb_gemm<true>(W_mid + (size_t)p * D * D, sW, sX, m, acc2, tid, r0, c0);
        }
    }
#pragma unroll
    for (int i = 0; i < 8; i++) {
        int pp = sE[r0 + i] >> 1;
#pragma unroll
        for (int p = 0; p < 4; p++) {
            U64F2 u; u.u = acc2[i][p];
            sX[(r0 + i) * FSTR + c0 + 2 * p]     = fmaxf(u.f.x + sBmd[pp * D + c0 + 2 * p], 0.f);
            sX[(r0 + i) * FSTR + c0 + 2 * p + 1] = fmaxf(u.f.y + sBmd[pp * D + c0 + 2 * p + 1], 0.f);
            acc2[i][p] = 0ull;
        }
    }

    fb_gemm<false>(W_root, sW, sX, m, acc2, tid, r0, c0);
#pragma unroll
    for (int i = 0; i < 8; i++) {
        float v[8];
#pragma unroll
        for (int p = 0; p < 4; p++) {
            U64F2 u; u.u = acc2[i][p];
            v[2 * p]     = fmaxf(u.f.x + sBrt[c0 + 2 * p],     0.f);
            v[2 * p + 1] = fmaxf(u.f.y + sBrt[c0 + 2 * p + 1], 0.f);
        }
        float4* o = reinterpret_cast<float4*>(out + (size_t)sOrig[r0 + i] * D + c0);
        o[0] = make_float4(v[0], v[1], v[2], v[3]);
        o[1] = make_float4(v[4], v[5], v[6], v[7]);
    }
}

// ======================= launch =======================
extern "C" void kernel_launch(void* const* d_in, const int* in_sizes, int n_in,
                              void* d_out, int out_size)
{
    const float* x      = (const float*)d_in[0];
    const float* Wg     = (const float*)d_in[1];
    const float* bg     = (const float*)d_in[2];
    const float* W_leaf = (const float*)d_in[3];
    const float* b_leaf = (const float*)d_in[4];
    const float* W_mid  = (const float*)d_in[5];
    const float* b_mid  = (const float*)d_in[6];
    const float* W_root = (const float*)d_in[7];
    const float* b_root = (const float*)d_in[8];
    float* out = (float*)d_out;

    cudaFuncSetAttribute(gate_kernel,
                         cudaFuncAttributeMaxDynamicSharedMemorySize, GATE_BYTES);
    cudaFuncSetAttribute(tree_mma_kernel,
                         cudaFuncAttributeMaxDynamicSharedMemorySize, MMA_SMEM);
    cudaFuncSetAttribute(fallback_kernel,
                         cudaFuncAttributeMaxDynamicSharedMemorySize, FB_BYTES);

    init_kernel<<<1, 32>>>();
    prep_w_kernel<<<7 * 65536 / 256, 256>>>(W_leaf, W_mid, W_root);
    gate_kernel<<<NB / GTILE, 256, GATE_BYTES>>>(x, Wg, bg);
    scan_kernel<<<1, 1>>>();
    scatter_kernel<<<NB / 256, 256>>>();
    tree_mma_kernel<<<NB / 128, 512, MMA_SMEM>>>(x, b_leaf, b_mid, b_root, out);
    fallback_kernel<<<NB / FTILE, 256, FB_BYTES>>>(
        x, W_leaf, b_leaf, W_mid, b_mid, W_root, b_root, out);
}

// round 7
// speedup vs baseline: 3.7412x; 1.0874x over previous
#include <cuda_runtime.h>
#include <cuda_bf16.h>
#include <cstdint>

#define NB      131072
#define D       256
#define LEAVES  4
#define MID     2

typedef unsigned long long u64;
union U64F2 { u64 u; float2 f; };

__device__ __forceinline__ uint32_t smem_u32(const void* p) {
    uint32_t a;
    asm("{ .reg .u64 t; cvta.to.shared.u64 t, %1; cvt.u32.u64 %0, t; }"
        : "=r"(a) : "l"(p));
    return a;
}

__device__ __forceinline__ uint32_t pack_bf2(__nv_bfloat16 a, __nv_bfloat16 b) {
    __nv_bfloat162 p = __halves2bfloat162(a, b);
    return *reinterpret_cast<uint32_t*>(&p);
}

// portable HMMA: m16n8k16 row.col f32.bf16.bf16.f32
__device__ __forceinline__
void mma_bf16(float* c, const uint32_t a[4], uint32_t b0, uint32_t b1)
{
    asm("mma.sync.aligned.m16n8k16.row.col.f32.bf16.bf16.f32 "
        "{%0,%1,%2,%3}, {%4,%5,%6,%7}, {%8,%9}, {%0,%1,%2,%3};"
        : "+f"(c[0]), "+f"(c[1]), "+f"(c[2]), "+f"(c[3])
        : "r"(a[0]), "r"(a[1]), "r"(a[2]), "r"(a[3]), "r"(b0), "r"(b1));
}

#define LDSM_X4(r0, r1, r2, r3, addr)                                        \
    asm volatile("ldmatrix.sync.aligned.m8n8.x4.shared.b16 {%0,%1,%2,%3}, [%4];" \
        : "=r"(r0), "=r"(r1), "=r"(r2), "=r"(r3) : "r"(addr))

// ======================= global scratch =======================
__device__ int g_idx[NB];
__device__ int g_perm[NB];
__device__ int g_hist[LEAVES];
__device__ int g_base[LEAVES];
// 7 mats x [hi|lo plane] x [n=256][k=256] bf16  (B col-major for mma.sync)
__device__ __align__(16) unsigned short g_wimg[7 * 2 * 65536];

// ======================= gate / sort =======================
constexpr int GTILE = 64;
constexpr int GSTR  = D + 8;
constexpr int GOFF_SX  = 0;
constexpr int GOFF_WG  = GOFF_SX + GTILE * GSTR;
constexpr int GOFF_LOG = GOFF_WG + D * LEAVES;
constexpr int GOFF_H   = GOFF_LOG + GTILE * LEAVES;
constexpr int GATE_BYTES = (GOFF_H + LEAVES) * (int)sizeof(float);

__global__ void init_kernel() {
    if (threadIdx.x < LEAVES) g_hist[threadIdx.x] = 0;
}

__global__ void __launch_bounds__(256, 2)
gate_kernel(const float* __restrict__ x, const float* __restrict__ Wg,
            const float* __restrict__ bg)
{
    extern __shared__ float sm[];
    float* sX = sm + GOFF_SX;  float* sWg = sm + GOFF_WG;
    float* sLog = sm + GOFF_LOG;
    int* sH = reinterpret_cast<int*>(sm + GOFF_H);
    const int tid = threadIdx.x;
    const size_t row0 = (size_t)blockIdx.x * GTILE;

    const float4* xg = reinterpret_cast<const float4*>(x + row0 * D);
#pragma unroll
    for (int i = 0; i < (GTILE * D / 4) / 256; i++) {
        int li = tid + i * 256;
        int r = li / (D / 4), c4 = li % (D / 4);
        float4 v = xg[r * (D / 4) + c4];
        float* dst = &sX[r * GSTR + c4 * 4];
        dst[0] = v.x; dst[1] = v.y; dst[2] = v.z; dst[3] = v.w;
    }
    for (int i = tid; i < D * LEAVES; i += 256) sWg[i] = Wg[i];
    if (tid < LEAVES) sH[tid] = 0;
    __syncthreads();
    {
        int r = tid & (GTILE - 1);
        int e = tid >> 6;
        float acc = bg[e];
        const float* xr = &sX[r * GSTR];
#pragma unroll 8
        for (int d = 0; d < D; d++) acc = fmaf(xr[d], sWg[d * LEAVES + e], acc);
        sLog[r * LEAVES + e] = acc;
    }
    __syncthreads();
    if (tid < GTILE) {
        float best = sLog[tid * LEAVES];
        int bi = 0;
#pragma unroll
        for (int e = 1; e < LEAVES; e++) {
            float v = sLog[tid * LEAVES + e];
            if (v > best) { best = v; bi = e; }
        }
        g_idx[row0 + tid] = bi;
        atomicAdd(&sH[bi], 1);
    }
    __syncthreads();
    if (tid < LEAVES) atomicAdd(&g_hist[tid], sH[tid]);
}

__global__ void scan_kernel() {
    int b = 0;
    for (int e = 0; e < LEAVES; e++) { g_base[e] = b; b += g_hist[e]; }
}

__global__ void scatter_kernel() {
    __shared__ int cnt[LEAVES];
    __shared__ int boff[LEAVES];
    const int tid = threadIdx.x;
    const int r = blockIdx.x * blockDim.x + tid;
    if (tid < LEAVES) cnt[tid] = 0;
    __syncthreads();
    int e = g_idx[r];
    int my = atomicAdd(&cnt[e], 1);
    __syncthreads();
    if (tid < LEAVES) boff[tid] = atomicAdd(&g_base[tid], cnt[tid]);
    __syncthreads();
    g_perm[boff[e] + my] = r;
}

// ======== weight prep: fp32 W[k][n] -> bf16 hi/lo images img[n][k] ========
__global__ void prep_w_kernel(const float* __restrict__ Wl,
                              const float* __restrict__ Wm,
                              const float* __restrict__ Wr)
{
    int gid = blockIdx.x * 256 + threadIdx.x;      // 7*65536 total
    int mat = gid >> 16;
    int rem = gid & 0xFFFF;
    int n = rem >> 8, k = rem & 255;
    float v;
    if (mat < 4)      v = Wl[mat * 65536 + k * 256 + n];
    else if (mat < 6) v = Wm[(mat - 4) * 65536 + k * 256 + n];
    else              v = Wr[k * 256 + n];
    __nv_bfloat16 h = __float2bfloat16(v);
    float lof = v - __bfloat162float(h);
    __nv_bfloat16 l = __float2bfloat16(lof);
    unsigned short* base = g_wimg + (size_t)mat * 131072;
    base[n * 256 + k]         = __bfloat16_as_ushort(h);
    base[65536 + n * 256 + k] = __bfloat16_as_ushort(l);
}

// ======================= main mma.sync kernel =======================
constexpr int A_STR_B   = 264 * 2;                 // 528
constexpr int OFF_AHI   = 0;
constexpr int OFF_ALO   = 67584;
constexpr int OFF_B     = 135168;
constexpr int B_PLANE_B = 256 * 40 * 2;            // 20480
constexpr int B_BUF_B   = 2 * B_PLANE_B;           // 40960
constexpr int OFF_BIAS  = OFF_B + 2 * B_BUF_B;     // 217088
constexpr int OFF_ORIG  = OFF_BIAS + 768 * 4;      // 220160
constexpr int MMA_SMEM  = OFF_ORIG + 512;          // 220672

__global__ void __launch_bounds__(512, 1)
tree_mma_kernel(const float* __restrict__ x,
                const float* __restrict__ b_leaf,
                const float* __restrict__ b_mid,
                const float* __restrict__ b_root,
                float* __restrict__ out)
{
    extern __shared__ char smc[];
    int* sOrig = reinterpret_cast<int*>(smc + OFF_ORIG);
    float* sBias = reinterpret_cast<float*>(smc + OFF_BIAS);
    const uint32_t sbU = smem_u32(smc);

    const int tid = threadIdx.x;
    const int lane = tid & 31, w = tid >> 5;
    const int wm = w & 3, wn = w >> 2;           // 4 x 4 warp grid
    const int g = lane >> 2, tg = lane & 3;
    const size_t row0 = (size_t)blockIdx.x * 128;

    if (tid < 128) sOrig[tid] = g_perm[row0 + tid];
    __syncthreads();
    const int eL = g_idx[sOrig[0]];
    if (eL != g_idx[sOrig[127]]) return;          // mixed tile -> fallback
    const int eM = eL >> 1;
    const int matIdx[3] = { eL, 4 + eM, 6 };

    for (int i = tid; i < 256; i += 512) {
        sBias[i]       = b_leaf[eL * 256 + i];
        sBias[256 + i] = b_mid[eM * 256 + i];
        sBias[512 + i] = b_root[i];
    }

    // ---- A init: thread -> (row tid>>2, 64-col segment tid&3), split hi/lo ----
    {
        int r = tid >> 2, seg = tid & 3;
        const float4* xr = reinterpret_cast<const float4*>(
                               x + (size_t)sOrig[r] * D) + seg * 16;
        char* aH = smc + OFF_AHI + r * A_STR_B + seg * 128;
        char* aL = smc + OFF_ALO + r * A_STR_B + seg * 128;
#pragma unroll
        for (int i = 0; i < 16; i++) {
            float4 f = xr[i];
            __nv_bfloat16 h0 = __float2bfloat16(f.x), h1 = __float2bfloat16(f.y);
            __nv_bfloat16 h2 = __float2bfloat16(f.z), h3 = __float2bfloat16(f.w);
            uint2 hv, lv;
            hv.x = pack_bf2(h0, h1);
            hv.y = pack_bf2(h2, h3);
            lv.x = pack_bf2(__float2bfloat16(f.x - __bfloat162float(h0)),
                            __float2bfloat16(f.y - __bfloat162float(h1)));
            lv.y = pack_bf2(__float2bfloat16(f.z - __bfloat162float(h2)),
                            __float2bfloat16(f.w - __bfloat162float(h3)));
            *reinterpret_cast<uint2*>(aH + i * 8) = hv;
            *reinterpret_cast<uint2*>(aL + i * 8) = lv;
        }
    }

    // ---- stage B chunk 0 of layer 0 into buffer 0 ----
    {
        int p = tid >> 8, n = tid & 255;
        const uint4* src = reinterpret_cast<const uint4*>(
            g_wimg + (size_t)matIdx[0] * 131072 + p * 65536 + n * 256);
        uint4* dst = reinterpret_cast<uint4*>(
            smc + OFF_B + p * B_PLANE_B + n * 80);
        dst[0] = src[0]; dst[1] = src[1]; dst[2] = src[2]; dst[3] = src[3];
    }
    __syncthreads();

    // ldmatrix base addresses (byte offsets in shared space)
    uint32_t aBaseH[2];
#pragma unroll
    for (int mt = 0; mt < 2; mt++)
        aBaseH[mt] = sbU + OFF_AHI
                   + (wm * 32 + mt * 16 + (lane & 15)) * A_STR_B
                   + (lane >> 4) * 16;
    const uint32_t bBase = sbU + OFF_B
        + (wn * 64 + (lane & 7) + ((lane >> 4) << 3)) * 80
        + (((lane >> 3) & 1) << 4);

    float acc[2][8][4];
#pragma unroll
    for (int mt = 0; mt < 2; mt++)
#pragma unroll
        for (int nt = 0; nt < 8; nt++)
#pragma unroll
            for (int q = 0; q < 4; q++) acc[mt][nt][q] = 0.f;

    int cur = 0;
    const int pfp = tid >> 8, pfn = tid & 255;     // B staging coords

#pragma unroll 1
    for (int l = 0; l < 3; l++) {
#pragma unroll 1
        for (int kc = 0; kc < 8; kc++) {
            // prefetch next chunk (next layer's chunk 0 at boundaries)
            bool hasNext = (kc < 7) || (l < 2);
            uint4 pf0, pf1, pf2, pf3;
            if (hasNext) {
                int nl  = (kc < 7) ? l : l + 1;
                int nkc = (kc < 7) ? kc + 1 : 0;
                const uint4* src = reinterpret_cast<const uint4*>(
                    g_wimg + (size_t)matIdx[nl] * 131072 + pfp * 65536
                    + pfn * 256 + nkc * 32);
                pf0 = src[0]; pf1 = src[1]; pf2 = src[2]; pf3 = src[3];
            }

            // ---- compute 2 k16-steps on buffer `cur` ----
#pragma unroll
            for (int kk = 0; kk < 2; kk++) {
                const uint32_t koffA = kc * 64 + kk * 32;
                uint32_t aH[2][4], aL[2][4];
#pragma unroll
                for (int mt = 0; mt < 2; mt++) {
                    LDSM_X4(aH[mt][0], aH[mt][1], aH[mt][2], aH[mt][3],
                            aBaseH[mt] + koffA);
                    LDSM_X4(aL[mt][0], aL[mt][1], aL[mt][2], aL[mt][3],
                            aBaseH[mt] + OFF_ALO + koffA);
                }
                const uint32_t bk = bBase + cur * B_BUF_B + kk * 32;
#pragma unroll
                for (int op = 0; op < 4; op++) {
                    uint32_t bh0, bh1, bh2, bh3, bl0, bl1, bl2, bl3;
                    LDSM_X4(bh0, bh1, bh2, bh3, bk + op * (16 * 80));
                    LDSM_X4(bl0, bl1, bl2, bl3, bk + op * (16 * 80) + B_PLANE_B);
#pragma unroll
                    for (int mt = 0; mt < 2; mt++) {
                        mma_bf16(acc[mt][2 * op],     aH[mt], bh0, bh1);
                        mma_bf16(acc[mt][2 * op],     aL[mt], bh0, bh1);
                        mma_bf16(acc[mt][2 * op],     aH[mt], bl0, bl1);
                        mma_bf16(acc[mt][2 * op + 1], aH[mt], bh2, bh3);
                        mma_bf16(acc[mt][2 * op + 1], aL[mt], bh2, bh3);
                        mma_bf16(acc[mt][2 * op + 1], aH[mt], bl2, bl3);
                    }
                }
            }

            if (hasNext) {
                uint4* dst = reinterpret_cast<uint4*>(
                    smc + OFF_B + (cur ^ 1) * B_BUF_B + pfp * B_PLANE_B + pfn * 80);
                dst[0] = pf0; dst[1] = pf1; dst[2] = pf2; dst[3] = pf3;
            }
            __syncthreads();
            cur ^= 1;
        }

        // ---- epilogue ----
        const float* sB = sBias + l * 256;
        if (l < 2) {
            // bias + relu + hi/lo split back into A planes
#pragma unroll
            for (int mt = 0; mt < 2; mt++) {
#pragma unroll
                for (int nt = 0; nt < 8; nt++) {
                    int col = wn * 64 + nt * 8 + tg * 2;
                    float b0 = sB[col], b1 = sB[col + 1];
                    int rlo = wm * 32 + mt * 16 + g;
#pragma unroll
                    for (int half = 0; half < 2; half++) {
                        int r = rlo + half * 8;
                        float v0 = fmaxf(acc[mt][nt][2 * half]     + b0, 0.f);
                        float v1 = fmaxf(acc[mt][nt][2 * half + 1] + b1, 0.f);
                        __nv_bfloat16 h0 = __float2bfloat16(v0);
                        __nv_bfloat16 h1 = __float2bfloat16(v1);
                        uint32_t hv = pack_bf2(h0, h1);
                        uint32_t lv = pack_bf2(
                            __float2bfloat16(v0 - __bfloat162float(h0)),
                            __float2bfloat16(v1 - __bfloat162float(h1)));
                        char* pa = smc + OFF_AHI + r * A_STR_B + col * 2;
                        *reinterpret_cast<uint32_t*>(pa) = hv;
                        *reinterpret_cast<uint32_t*>(pa + OFF_ALO) = lv;
                        acc[mt][nt][2 * half] = 0.f;
                        acc[mt][nt][2 * half + 1] = 0.f;
                    }
                }
            }
            __syncthreads();
        } else {
            // bias + relu + scatter to original rows
#pragma unroll
            for (int mt = 0; mt < 2; mt++) {
#pragma unroll
                for (int half = 0; half < 2; half++) {
                    int r = wm * 32 + mt * 16 + g + half * 8;
                    float* orow = out + (size_t)sOrig[r] * D;
#pragma unroll
                    for (int nt = 0; nt < 8; nt++) {
                        int col = wn * 64 + nt * 8 + tg * 2;
                        float2 v;
                        v.x = fmaxf(acc[mt][nt][2 * half]     + sB[col],     0.f);
                        v.y = fmaxf(acc[mt][nt][2 * half + 1] + sB[col + 1], 0.f);
                        *reinterpret_cast<float2*>(orow + col) = v;
                    }
                }
            }
        }
    }
}

// ======================= FFMA2 fallback for mixed 128-tiles =======================
constexpr int FTILE = 64;
constexpr int FKC = 16;
constexpr int FSTR = D + 8;
constexpr int FOFF_SX = 0;
constexpr int FOFF_SW = FOFF_SX + FTILE * FSTR;
constexpr int FOFF_BLEAF = FOFF_SW + FKC * D;
constexpr int FOFF_BMID = FOFF_BLEAF + LEAVES * D;
constexpr int FOFF_BROOT = FOFF_BMID + MID * D;
constexpr int FOFF_ORIG = FOFF_BROOT + D;
constexpr int FOFF_E = FOFF_ORIG + FTILE;
constexpr int FOFF_MM = FOFF_E + FTILE;
constexpr int FB_BYTES = (FOFF_MM + 2) * (int)sizeof(float);

#define FMA_F32X2(d, a, b, c) \
    asm("fma.rn.f32x2 %0, %1, %2, %3;" : "=l"(d) : "l"(a), "l"(b), "l"(c))
#define PACK2(d, xx) \
    asm("mov.b64 %0, {%1, %1};" : "=l"(d) : "r"(xx))

template <bool MASKED>
__device__ __forceinline__
void fb_gemm(const float* __restrict__ Wglob, float* sW, const float* sX,
             const float m[8], u64 (&acc2)[8][4], int tid, int r0, int c0)
{
#pragma unroll 1
    for (int kc = 0; kc < D; kc += FKC) {
        __syncthreads();
        const float4* wg4 = reinterpret_cast<const float4*>(Wglob + (size_t)kc * D);
        float4* sW4 = reinterpret_cast<float4*>(sW);
#pragma unroll
        for (int i = 0; i < (FKC * D / 4) / 256; i++)
            sW4[tid + i * 256] = wg4[tid + i * 256];
        __syncthreads();
#pragma unroll
        for (int k4 = 0; k4 < FKC; k4 += 4) {
            float4 a4[8];
#pragma unroll
            for (int i = 0; i < 8; i++) {
                a4[i] = *reinterpret_cast<const float4*>(&sX[(r0 + i) * FSTR + kc + k4]);
                if (MASKED) {
                    a4[i].x *= m[i]; a4[i].y *= m[i];
                    a4[i].z *= m[i]; a4[i].w *= m[i];
                }
            }
#pragma unroll
            for (int kk = 0; kk < 4; kk++) {
                const ulonglong2* bp =
                    reinterpret_cast<const ulonglong2*>(&sW[(k4 + kk) * D + c0]);
                ulonglong2 b01 = bp[0];
                ulonglong2 b23 = bp[1];
#pragma unroll
                for (int i = 0; i < 8; i++) {
                    float av = (kk == 0) ? a4[i].x : (kk == 1) ? a4[i].y
                             : (kk == 2) ? a4[i].z : a4[i].w;
                    u64 a2;
                    PACK2(a2, __float_as_uint(av));
                    FMA_F32X2(acc2[i][0], a2, b01.x, acc2[i][0]);
                    FMA_F32X2(acc2[i][1], a2, b01.y, acc2[i][1]);
                    FMA_F32X2(acc2[i][2], a2, b23.x, acc2[i][2]);
                    FMA_F32X2(acc2[i][3], a2, b23.y, acc2[i][3]);
                }
            }
        }
    }
}

__global__ void __launch_bounds__(256, 2)
fallback_kernel(const float* __restrict__ x,
                const float* __restrict__ W_leaf, const float* __restrict__ b_leaf,
                const float* __restrict__ W_mid,  const float* __restrict__ b_mid,
                const float* __restrict__ W_root, const float* __restrict__ b_root,
                float* __restrict__ out)
{
    // only process 64-tiles whose containing 128-tile is expert-mixed
    const size_t t128 = (size_t)(blockIdx.x >> 1) * 128;
    if (g_idx[g_perm[t128]] == g_idx[g_perm[t128 + 127]]) return;

    extern __shared__ float sm[];
    float* sX = sm + FOFF_SX;  float* sW = sm + FOFF_SW;
    float* sBlf = sm + FOFF_BLEAF;  float* sBmd = sm + FOFF_BMID;
    float* sBrt = sm + FOFF_BROOT;
    int* sOrig = reinterpret_cast<int*>(sm + FOFF_ORIG);
    int* sE = reinterpret_cast<int*>(sm + FOFF_E);
    int* sMM = reinterpret_cast<int*>(sm + FOFF_MM);

    const int tid = threadIdx.x;
    const size_t row0 = (size_t)blockIdx.x * FTILE;
    const int tx = tid & 31, ty = tid >> 5;
    const int r0 = ty * 8, c0 = tx * 8;

    if (tid < FTILE) {
        int orig = g_perm[row0 + tid];
        sOrig[tid] = orig;
        sE[tid] = g_idx[orig];
    }
    if (tid == FTILE) { sMM[0] = LEAVES; sMM[1] = -1; }
    __syncthreads();

#pragma unroll
    for (int i = 0; i < (FTILE * D / 4) / 256; i++) {
        int li = tid + i * 256;
        int r = li / (D / 4), c4 = li % (D / 4);
        const float4* src = reinterpret_cast<const float4*>(x + (size_t)sOrig[r] * D);
        float4 v = src[c4];
        float* dst = &sX[r * FSTR + c4 * 4];
        dst[0] = v.x; dst[1] = v.y; dst[2] = v.z; dst[3] = v.w;
    }
    for (int i = tid; i < LEAVES * D; i += 256) sBlf[i] = b_leaf[i];
    for (int i = tid; i < MID * D;    i += 256) sBmd[i] = b_mid[i];
    for (int i = tid; i < D;          i += 256) sBrt[i] = b_root[i];
    if (tid < FTILE) {
        atomicMin(&sMM[0], sE[tid]);
        atomicMax(&sMM[1], sE[tid]);
    }
    __syncthreads();

    const int emin = sMM[0], emax = sMM[1];
    u64 acc2[8][4];
#pragma unroll
    for (int i = 0; i < 8; i++)
#pragma unroll
        for (int j = 0; j < 4; j++) acc2[i][j] = 0ull;
    float m[8];

    if (emin == emax) {
        fb_gemm<false>(W_leaf + (size_t)emin * D * D, sW, sX, m, acc2, tid, r0, c0);
    } else {
        for (int e = emin; e <= emax; e++) {
#pragma unroll
            for (int i = 0; i < 8; i++) m[i] = (sE[r0 + i] == e) ? 1.f : 0.f;
            fb_gemm<true>(W_leaf + (size_t)e * D * D, sW, sX, m, acc2, tid, r0, c0);
        }
    }
#pragma unroll
    for (int i = 0; i < 8; i++) {
        int e = sE[r0 + i];
#pragma unroll
        for (int p = 0; p < 4; p++) {
            U64F2 u; u.u = acc2[i][p];
            sX[(r0 + i) * FSTR + c0 + 2 * p]     = fmaxf(u.f.x + sBlf[e * D + c0 + 2 * p], 0.f);
            sX[(r0 + i) * FSTR + c0 + 2 * p + 1] = fmaxf(u.f.y + sBlf[e * D + c0 + 2 * p + 1], 0.f);
            acc2[i][p] = 0ull;
        }
    }

    const int pmin = emin >> 1, pmax = emax >> 1;
    if (pmin == pmax) {
        fb_gemm<false>(W_mid + (size_t)pmin * D * D, sW, sX, m, acc2, tid, r0, c0);
    } else {
        for (int p = pmin; p <= pmax; p++) {
#pragma unroll
            for (int i = 0; i < 8; i++) m[i] = ((sE[r0 + i] >> 1) == p) ? 1.f : 0.f;
            fb_gemm<true>(W_mid + (size_t)p * D * D, sW, sX, m, acc2, tid, r0, c0);
        }
    }
#pragma unroll
    for (int i = 0; i < 8; i++) {
        int pp = sE[r0 + i] >> 1;
#pragma unroll
        for (int p = 0; p < 4; p++) {
            U64F2 u; u.u = acc2[i][p];
            sX[(r0 + i) * FSTR + c0 + 2 * p]     = fmaxf(u.f.x + sBmd[pp * D + c0 + 2 * p], 0.f);
            sX[(r0 + i) * FSTR + c0 + 2 * p + 1] = fmaxf(u.f.y + sBmd[pp * D + c0 + 2 * p + 1], 0.f);
            acc2[i][p] = 0ull;
        }
    }

    fb_gemm<false>(W_root, sW, sX, m, acc2, tid, r0, c0);
#pragma unroll
    for (int i = 0; i < 8; i++) {
        float v[8];
#pragma unroll
        for (int p = 0; p < 4; p++) {
            U64F2 u; u.u = acc2[i][p];
            v[2 * p]     = fmaxf(u.f.x + sBrt[c0 + 2 * p],     0.f);
            v[2 * p + 1] = fmaxf(u.f.y + sBrt[c0 + 2 * p + 1], 0.f);
        }
        float4* o = reinterpret_cast<float4*>(out + (size_t)sOrig[r0 + i] * D + c0);
        o[0] = make_float4(v[0], v[1], v[2], v[3]);
        o[1] = make_float4(v[4], v[5], v[6], v[7]);
    }
}

// ======================= launch =======================
extern "C" void kernel_launch(void* const* d_in, const int* in_sizes, int n_in,
                              void* d_out, int out_size)
{
    const float* x      = (const float*)d_in[0];
    const float* Wg     = (const float*)d_in[1];
    const float* bg     = (const float*)d_in[2];
    const float* W_leaf = (const float*)d_in[3];
    const float* b_leaf = (const float*)d_in[4];
    const float* W_mid  = (const float*)d_in[5];
    const float* b_mid  = (const float*)d_in[6];
    const float* W_root = (const float*)d_in[7];
    const float* b_root = (const float*)d_in[8];
    float* out = (float*)d_out;

    cudaFuncSetAttribute(gate_kernel,
                         cudaFuncAttributeMaxDynamicSharedMemorySize, GATE_BYTES);
    cudaFuncSetAttribute(tree_mma_kernel,
                         cudaFuncAttributeMaxDynamicSharedMemorySize, MMA_SMEM);
    cudaFuncSetAttribute(fallback_kernel,
                         cudaFuncAttributeMaxDynamicSharedMemorySize, FB_BYTES);

    init_kernel<<<1, 32>>>();
    prep_w_kernel<<<7 * 65536 / 256, 256>>>(W_leaf, W_mid, W_root);
    gate_kernel<<<NB / GTILE, 256, GATE_BYTES>>>(x, Wg, bg);
    scan_kernel<<<1, 1>>>();
    scatter_kernel<<<NB / 256, 256>>>();
    tree_mma_kernel<<<NB / 128, 512, MMA_SMEM>>>(x, b_leaf, b_mid, b_root, out);
    fallback_kernel<<<NB / FTILE, 256, FB_BYTES>>>(
        x, W_leaf, b_leaf, W_mid, b_mid, W_root, b_root, out);
}